// round 2
// baseline (speedup 1.0000x reference)
#include <cuda_runtime.h>
#include <math_constants.h>

#define BATCH 16
#define SEQ 4096
#define HKV 8
#define GQ 4            // q_mult
#define HQ 32
#define DIM 128
#define SPLITS 16
#define CHUNK (SEQ / SPLITS)   // 256
#define NWARP 8
#define NTHREADS 256

// Scratch for split partials (no allocations allowed -> device globals)
// slot = ((b*HKV + h)*GQ + g)*SPLITS + split   -> 16*8*4*16 = 8192 slots
__device__ float g_Pacc[BATCH * HKV * GQ * SPLITS * DIM]; // 4 MB
__device__ float g_Pm[BATCH * HKV * GQ * SPLITS];
__device__ float g_Pl[BATCH * HKV * GQ * SPLITS];

__device__ __forceinline__ float warp_sum(float v) {
    v += __shfl_xor_sync(0xffffffffu, v, 16);
    v += __shfl_xor_sync(0xffffffffu, v, 8);
    v += __shfl_xor_sync(0xffffffffu, v, 4);
    v += __shfl_xor_sync(0xffffffffu, v, 2);
    v += __shfl_xor_sync(0xffffffffu, v, 1);
    return v;
}

__global__ __launch_bounds__(NTHREADS) void attn_partial_kernel(
    const float* __restrict__ Q,
    const float* __restrict__ Knew,
    const float* __restrict__ Vnew,
    const float* __restrict__ Kc,
    const float* __restrict__ Vc,
    const float* __restrict__ mask)
{
    const int split = blockIdx.x;
    const int h     = blockIdx.y;
    const int b     = blockIdx.z;
    const int tid   = threadIdx.x;
    const int wid   = tid >> 5;
    const int lane  = tid & 31;

    const float scale = 0.08838834764831845f; // 1/sqrt(128)

    // Q for the 4 grouped heads, pre-scaled, in registers (lane owns dims 4*lane..+3)
    float4 q[GQ];
#pragma unroll
    for (int g = 0; g < GQ; ++g) {
        const float* qp = Q + ((size_t)b * HQ + (h * GQ + g)) * DIM + lane * 4;
        float4 t = *reinterpret_cast<const float4*>(qp);
        q[g].x = t.x * scale; q[g].y = t.y * scale;
        q[g].z = t.z * scale; q[g].w = t.w * scale;
    }

    const int t0 = split * CHUNK;
    const int nt = (split == SPLITS - 1) ? (CHUNK + 1) : CHUNK; // last split owns new token

    float m[GQ], l[GQ];
    float4 acc[GQ];
#pragma unroll
    for (int g = 0; g < GQ; ++g) {
        m[g] = -CUDART_INF_F; l[g] = 0.f;
        acc[g] = make_float4(0.f, 0.f, 0.f, 0.f);
    }

    // --- streaming loop with one-deep prefetch ---
    int i = wid;
    float4 kv, vv; float mv = 0.f;
    if (i < nt) {
        int t = t0 + i;
        if (t < SEQ) {
            size_t row = (((size_t)b * SEQ + t) * HKV + h) * DIM + lane * 4;
            kv = *reinterpret_cast<const float4*>(Kc + row);
            vv = *reinterpret_cast<const float4*>(Vc + row);
            mv = __ldg(mask + (size_t)b * SEQ + t);
        } else {
            size_t row = ((size_t)b * HKV + h) * DIM + lane * 4;
            kv = *reinterpret_cast<const float4*>(Knew + row);
            vv = *reinterpret_cast<const float4*>(Vnew + row);
            mv = 0.f;
        }
    }

    while (i < nt) {
        const int inext = i + NWARP;
        float4 kn, vn; float mn2 = 0.f;
        if (inext < nt) {
            int t = t0 + inext;
            if (t < SEQ) {
                size_t row = (((size_t)b * SEQ + t) * HKV + h) * DIM + lane * 4;
                kn = *reinterpret_cast<const float4*>(Kc + row);
                vn = *reinterpret_cast<const float4*>(Vc + row);
                mn2 = __ldg(mask + (size_t)b * SEQ + t);
            } else {
                size_t row = ((size_t)b * HKV + h) * DIM + lane * 4;
                kn = *reinterpret_cast<const float4*>(Knew + row);
                vn = *reinterpret_cast<const float4*>(Vnew + row);
                mn2 = 0.f;
            }
        }

        // scores for 4 heads
        float s[GQ];
#pragma unroll
        for (int g = 0; g < GQ; ++g) {
            float d = q[g].x * kv.x + q[g].y * kv.y + q[g].z * kv.z + q[g].w * kv.w;
            s[g] = warp_sum(d) + mv;
        }
        // online softmax update
#pragma unroll
        for (int g = 0; g < GQ; ++g) {
            float mn = fmaxf(m[g], s[g]);
            float c = __expf(m[g] - mn);
            float p = __expf(s[g] - mn);
            l[g] = l[g] * c + p;
            acc[g].x = acc[g].x * c + p * vv.x;
            acc[g].y = acc[g].y * c + p * vv.y;
            acc[g].z = acc[g].z * c + p * vv.z;
            acc[g].w = acc[g].w * c + p * vv.w;
            m[g] = mn;
        }

        kv = kn; vv = vn; mv = mn2;
        i = inext;
    }

    // --- cross-warp combine in shared memory ---
    __shared__ float sm_m[NWARP][GQ];
    __shared__ float sm_l[NWARP][GQ];
    __shared__ float sm_acc[NWARP][GQ][DIM];

#pragma unroll
    for (int g = 0; g < GQ; ++g) {
        sm_acc[wid][g][lane * 4 + 0] = acc[g].x;
        sm_acc[wid][g][lane * 4 + 1] = acc[g].y;
        sm_acc[wid][g][lane * 4 + 2] = acc[g].z;
        sm_acc[wid][g][lane * 4 + 3] = acc[g].w;
    }
    if (lane < GQ) { sm_m[wid][lane] = m[lane]; sm_l[wid][lane] = l[lane]; }
    __syncthreads();

    // 512 (g,d) pairs, 256 threads -> 2 each
    for (int p = tid; p < GQ * DIM; p += NTHREADS) {
        const int g = p >> 7;
        const int d = p & (DIM - 1);
        float M = -CUDART_INF_F;
#pragma unroll
        for (int w = 0; w < NWARP; ++w) M = fmaxf(M, sm_m[w][g]);
        float L = 0.f, A = 0.f;
#pragma unroll
        for (int w = 0; w < NWARP; ++w) {
            float e = __expf(sm_m[w][g] - M);
            L += sm_l[w][g] * e;
            A += sm_acc[w][g][d] * e;
        }
        const int slot = (((b * HKV + h) * GQ + g) * SPLITS) + split;
        g_Pacc[(size_t)slot * DIM + d] = A;
        if (d == 0) { g_Pm[slot] = M; g_Pl[slot] = L; }
    }
}

__global__ __launch_bounds__(DIM) void attn_reduce_kernel(float* __restrict__ out)
{
    const int u = blockIdx.x;     // u = b*32 + (h*4+g), 0..511
    const int d = threadIdx.x;    // 0..127

    float M = -CUDART_INF_F;
#pragma unroll
    for (int s = 0; s < SPLITS; ++s) M = fmaxf(M, g_Pm[u * SPLITS + s]);
    float L = 0.f, A = 0.f;
#pragma unroll
    for (int s = 0; s < SPLITS; ++s) {
        float e = __expf(g_Pm[u * SPLITS + s] - M);
        L += g_Pl[u * SPLITS + s] * e;
        A += g_Pacc[(size_t)(u * SPLITS + s) * DIM + d] * e;
    }
    out[(size_t)u * DIM + d] = A / L;
}

extern "C" void kernel_launch(void* const* d_in, const int* in_sizes, int n_in,
                              void* d_out, int out_size)
{
    const float* Q    = (const float*)d_in[0];
    const float* K    = (const float*)d_in[1];
    const float* V    = (const float*)d_in[2];
    const float* Kc   = (const float*)d_in[3];
    const float* Vc   = (const float*)d_in[4];
    const float* mask = (const float*)d_in[5];
    float* out = (float*)d_out;

    dim3 grid(SPLITS, HKV, BATCH);
    attn_partial_kernel<<<grid, NTHREADS>>>(Q, K, V, Kc, Vc, mask);
    attn_reduce_kernel<<<BATCH * HQ, DIM>>>(out);
}

// round 3
// speedup vs baseline: 1.0437x; 1.0437x over previous
#include <cuda_runtime.h>
#include <math_constants.h>

#define BATCH 16
#define SEQ 4096
#define HKV 8
#define GQ 4
#define HQ 32
#define DIM 128
#define SPLITS 8
#define CHUNK (SEQ / SPLITS)      // 512 tokens per CTA
#define STOK 16                   // tokens per stage
#define NSTAGE 3
#define NS (CHUNK / STOK)         // 32 stages
#define NWARP 8
#define NTHREADS 256

// split partials scratch: slot = ((b*HKV+h)*GQ+g)*SPLITS + split -> 4096 slots
__device__ float g_Pacc[BATCH * HKV * GQ * SPLITS * DIM]; // 2 MB
__device__ float g_Pm[BATCH * HKV * GQ * SPLITS];
__device__ float g_Pl[BATCH * HKV * GQ * SPLITS];

__device__ __forceinline__ float warp_sum(float v) {
    v += __shfl_xor_sync(0xffffffffu, v, 16);
    v += __shfl_xor_sync(0xffffffffu, v, 8);
    v += __shfl_xor_sync(0xffffffffu, v, 4);
    v += __shfl_xor_sync(0xffffffffu, v, 2);
    v += __shfl_xor_sync(0xffffffffu, v, 1);
    return v;
}

__device__ __forceinline__ void cp16(float* smem, const float* gmem) {
    unsigned s = (unsigned)__cvta_generic_to_shared(smem);
    asm volatile("cp.async.cg.shared.global [%0], [%1], 16;" :: "r"(s), "l"(gmem));
}

__global__ __launch_bounds__(NTHREADS) void attn_partial_kernel(
    const float* __restrict__ Q,
    const float* __restrict__ Knew,
    const float* __restrict__ Vnew,
    const float* __restrict__ Kc,
    const float* __restrict__ Vc,
    const float* __restrict__ mask)
{
    // 48 KB pool: stages sK[3][16][128] | sV[3][16][128]; overlaid by the
    // cross-warp combine buffers after the mainloop drains.
    __shared__ __align__(16) float pool[NSTAGE * STOK * DIM * 2]; // 12288 floats = 48KB
    float* sK = pool;                                  // [NSTAGE][STOK][DIM]
    float* sV = pool + NSTAGE * STOK * DIM;            // [NSTAGE][STOK][DIM]

    const int split = blockIdx.x;
    const int h     = blockIdx.y;
    const int b     = blockIdx.z;
    const int tid   = threadIdx.x;
    const int wid   = tid >> 5;
    const int lane  = tid & 31;

    const float scale = 0.08838834764831845f; // 1/sqrt(128)
    const int t0 = split * CHUNK;

    // Q for the 4 grouped heads, pre-scaled (lane owns dims 4*lane..+3)
    float4 q[GQ];
#pragma unroll
    for (int g = 0; g < GQ; ++g) {
        const float* qp = Q + ((size_t)b * HQ + (h * GQ + g)) * DIM + lane * 4;
        float4 t = *reinterpret_cast<const float4*>(qp);
        q[g].x = t.x * scale; q[g].y = t.y * scale;
        q[g].z = t.z * scale; q[g].w = t.w * scale;
    }

    // stage loader: 512 float4 per tensor, 2 per thread per tensor
    auto load_stage = [&](int st, int slot) {
#pragma unroll
        for (int j = 0; j < 2; ++j) {
            const int e   = tid * 2 + j;          // 0..511
            const int row = e >> 5;               // 0..15
            const int c4  = e & 31;               // 0..31
            const int t   = t0 + st * STOK + row;
            const size_t goff = (((size_t)b * SEQ + t) * HKV + h) * DIM + c4 * 4;
            cp16(sK + (slot * STOK + row) * DIM + c4 * 4, Kc + goff);
            cp16(sV + (slot * STOK + row) * DIM + c4 * 4, Vc + goff);
        }
        asm volatile("cp.async.commit_group;");
    };

    // prologue: 2 stages in flight
    load_stage(0, 0);
    load_stage(1, 1);

    float m[GQ], l[GQ];
    float4 acc[GQ];
#pragma unroll
    for (int g = 0; g < GQ; ++g) {
        m[g] = -CUDART_INF_F; l[g] = 0.f;
        acc[g] = make_float4(0.f, 0.f, 0.f, 0.f);
    }

    for (int s = 0; s < NS; ++s) {
        const int slot = s % NSTAGE;
        if (s + 2 < NS) asm volatile("cp.async.wait_group 1;");
        else            asm volatile("cp.async.wait_group 0;");
        __syncthreads();

        // this warp's 2 tokens of the stage
        const int tl0 = wid * 2;
        const int tl1 = wid * 2 + 1;
        const int tg0 = t0 + s * STOK + tl0;
        const int tg1 = tg0 + 1;
        const float mv0 = __ldg(mask + (size_t)b * SEQ + tg0);
        const float mv1 = __ldg(mask + (size_t)b * SEQ + tg1);

        const float4 k0 = *reinterpret_cast<const float4*>(sK + (slot * STOK + tl0) * DIM + lane * 4);
        const float4 k1 = *reinterpret_cast<const float4*>(sK + (slot * STOK + tl1) * DIM + lane * 4);
        const float4 v0 = *reinterpret_cast<const float4*>(sV + (slot * STOK + tl0) * DIM + lane * 4);
        const float4 v1 = *reinterpret_cast<const float4*>(sV + (slot * STOK + tl1) * DIM + lane * 4);

        float s0[GQ], s1[GQ];
#pragma unroll
        for (int g = 0; g < GQ; ++g) {
            s0[g] = q[g].x * k0.x + q[g].y * k0.y + q[g].z * k0.z + q[g].w * k0.w;
            s1[g] = q[g].x * k1.x + q[g].y * k1.y + q[g].z * k1.z + q[g].w * k1.w;
        }
#pragma unroll
        for (int g = 0; g < GQ; ++g) { s0[g] = warp_sum(s0[g]); s1[g] = warp_sum(s1[g]); }

#pragma unroll
        for (int g = 0; g < GQ; ++g) {
            const float a0 = s0[g] + mv0;
            const float a1 = s1[g] + mv1;
            const float mn = fmaxf(m[g], fmaxf(a0, a1));
            const float c  = __expf(m[g] - mn);
            const float p0 = __expf(a0 - mn);
            const float p1 = __expf(a1 - mn);
            l[g] = l[g] * c + p0 + p1;
            acc[g].x = acc[g].x * c + p0 * v0.x + p1 * v1.x;
            acc[g].y = acc[g].y * c + p0 * v0.y + p1 * v1.y;
            acc[g].z = acc[g].z * c + p0 * v0.z + p1 * v1.z;
            acc[g].w = acc[g].w * c + p0 * v0.w + p1 * v1.w;
            m[g] = mn;
        }

        __syncthreads();
        if (s + 2 < NS) load_stage(s + 2, (s + 2) % NSTAGE);
    }

    // epilogue: last split's warp 0 folds in the appended token
    if (split == SPLITS - 1 && wid == 0) {
        const size_t row = ((size_t)b * HKV + h) * DIM + lane * 4;
        const float4 kn = *reinterpret_cast<const float4*>(Knew + row);
        const float4 vn = *reinterpret_cast<const float4*>(Vnew + row);
        float sn[GQ];
#pragma unroll
        for (int g = 0; g < GQ; ++g)
            sn[g] = q[g].x * kn.x + q[g].y * kn.y + q[g].z * kn.z + q[g].w * kn.w;
#pragma unroll
        for (int g = 0; g < GQ; ++g) sn[g] = warp_sum(sn[g]);
#pragma unroll
        for (int g = 0; g < GQ; ++g) {
            const float mn = fmaxf(m[g], sn[g]);
            const float c  = __expf(m[g] - mn);
            const float p  = __expf(sn[g] - mn);
            l[g] = l[g] * c + p;
            acc[g].x = acc[g].x * c + p * vn.x;
            acc[g].y = acc[g].y * c + p * vn.y;
            acc[g].z = acc[g].z * c + p * vn.z;
            acc[g].w = acc[g].w * c + p * vn.w;
            m[g] = mn;
        }
    }

    // cross-warp combine (overlay onto the drained stage pool)
    __syncthreads();
    float* ovA = pool;                       // [NWARP][GQ][DIM]
    float* ovM = pool + NWARP * GQ * DIM;    // [NWARP][GQ]
    float* ovL = ovM + NWARP * GQ;           // [NWARP][GQ]

#pragma unroll
    for (int g = 0; g < GQ; ++g) {
        float* dst = ovA + ((wid * GQ + g) * DIM) + lane * 4;
        dst[0] = acc[g].x; dst[1] = acc[g].y; dst[2] = acc[g].z; dst[3] = acc[g].w;
    }
    if (lane < GQ) { ovM[wid * GQ + lane] = m[lane]; ovL[wid * GQ + lane] = l[lane]; }
    __syncthreads();

    for (int p = tid; p < GQ * DIM; p += NTHREADS) {
        const int g = p >> 7;
        const int d = p & (DIM - 1);
        float M = -CUDART_INF_F;
#pragma unroll
        for (int w = 0; w < NWARP; ++w) M = fmaxf(M, ovM[w * GQ + g]);
        float L = 0.f, A = 0.f;
#pragma unroll
        for (int w = 0; w < NWARP; ++w) {
            const float e = __expf(ovM[w * GQ + g] - M);
            L += ovL[w * GQ + g] * e;
            A += ovA[(w * GQ + g) * DIM + d] * e;
        }
        const int slot = (((b * HKV + h) * GQ + g) * SPLITS) + split;
        g_Pacc[(size_t)slot * DIM + d] = A;
        if (d == 0) { g_Pm[slot] = M; g_Pl[slot] = L; }
    }
}

__global__ __launch_bounds__(DIM) void attn_reduce_kernel(float* __restrict__ out)
{
    const int u = blockIdx.x;   // b*32 + h*4 + g
    const int d = threadIdx.x;

    float M = -CUDART_INF_F;
#pragma unroll
    for (int s = 0; s < SPLITS; ++s) M = fmaxf(M, g_Pm[u * SPLITS + s]);
    float L = 0.f, A = 0.f;
#pragma unroll
    for (int s = 0; s < SPLITS; ++s) {
        const float e = __expf(g_Pm[u * SPLITS + s] - M);
        L += g_Pl[u * SPLITS + s] * e;
        A += g_Pacc[(size_t)(u * SPLITS + s) * DIM + d] * e;
    }
    out[(size_t)u * DIM + d] = A / L;
}

extern "C" void kernel_launch(void* const* d_in, const int* in_sizes, int n_in,
                              void* d_out, int out_size)
{
    const float* Q    = (const float*)d_in[0];
    const float* K    = (const float*)d_in[1];
    const float* V    = (const float*)d_in[2];
    const float* Kc   = (const float*)d_in[3];
    const float* Vc   = (const float*)d_in[4];
    const float* mask = (const float*)d_in[5];
    float* out = (float*)d_out;

    dim3 grid(SPLITS, HKV, BATCH);
    attn_partial_kernel<<<grid, NTHREADS>>>(Q, K, V, Kc, Vc, mask);
    attn_reduce_kernel<<<BATCH * HQ, DIM>>>(out);
}